// round 1
// baseline (speedup 1.0000x reference)
#include <cuda_runtime.h>

#define T_TOTAL 4015
#define NWARM   365
#define NBAS    2048

__device__ __forceinline__ float sqrt_ap(float x){ float y; asm("sqrt.approx.f32 %0, %1;" : "=f"(y) : "f"(x)); return y; }
__device__ __forceinline__ float rsqrt_ap(float x){ float y; asm("rsqrt.approx.f32 %0, %1;" : "=f"(y) : "f"(x)); return y; }

struct St {
  float s, r;
  float x1, inv_x1, x2, inv_x3;
  float u10,u11,u12;
  float u20,u21,u22,u23,u24,u25;
  float h1,h2,h3,h4,h5;   // pr history for the causal convs
  float q9p,q1p;          // conv outputs for the step whose routing is pending
};

// Production store update. Returns pr. tanh args are <= 0.01 (pn<=1, x1>=100),
// so a 2-term Taylor is exact to ~1e-11.
__device__ __forceinline__ float prod_step(St& st, float2 pe){
  float pn = fmaxf(pe.x - pe.y, 0.f);
  float en = fmaxf(pe.y - pe.x, 0.f);
  float xp = pn * st.inv_x1;
  float xe = en * st.inv_x1;
  float tp = xp * fmaf(xp*xp, -(1.f/3.f), 1.f);
  float te = xe * fmaf(xe*xe, -(1.f/3.f), 1.f);
  float u  = st.s * st.inv_x1;
  float ps = __fdividef(st.x1 * fmaf(-u, u, 1.f) * tp, fmaf(u, tp, 1.f));
  float es = __fdividef(st.s * (2.f - u) * te,        fmaf(1.f - u, te, 1.f));
  float s2 = st.s - es + ps;
  s2 = fminf(fmaxf(s2, 0.f), st.x1);
  float z  = (4.f/9.f) * s2 * st.inv_x1;
  float z2 = z * z;
  float w  = rsqrt_ap(sqrt_ap(fmaf(z2, z2, 1.f)));  // (1+z^4)^(-1/4)
  float snew = s2 * w;                               // s2 - perc
  float pr = (s2 - snew) + (pn - ps);                // perc + (pn - ps)
  st.s = snew;
  return pr;
}

// Routing store update for the pending step (uses st.q9p/st.q1p). Returns q.
__device__ __forceinline__ float route_step(St& st){
  float v   = st.r * st.inv_x3;                      // in [0,1)
  float gex = st.x2 * (v*v*v) * sqrt_ap(v);          // x2 * v^3.5
  float r2  = fmaxf(0.f, st.r + st.q9p + gex);
  float wv  = r2 * st.inv_x3;
  float wv2 = wv * wv;
  float w   = rsqrt_ap(sqrt_ap(fmaf(wv2, wv2, 1.f)));
  float rnew = r2 * w;                               // r2 - qr
  float q  = (r2 - rnew) + fmaxf(0.f, st.q1p + gex); // qr + qd
  st.r = rnew;
  return q;
}

__device__ __forceinline__ void conv_update(St& st, float pr){
  st.q9p = st.u10*pr + st.u11*st.h1 + st.u12*st.h2;
  st.q1p = st.u20*pr + st.u21*st.h1 + st.u22*st.h2
         + st.u23*st.h3 + st.u24*st.h4 + st.u25*st.h5;
  st.h5 = st.h4; st.h4 = st.h3; st.h3 = st.h2; st.h2 = st.h1; st.h1 = pr;
}

// One pipelined iteration at time t (1..4014): routing for t-1, production for t.
__device__ __forceinline__ void iter(St& st, int t, float2 pe,
                                     float* __restrict__ out, int b){
  float q = route_step(st);
  int to = t - 1 - NWARM;
  if (to >= 0) out[to * NBAS + b] = q;
  if (t == NWARM){ st.h1=0.f; st.h2=0.f; st.h3=0.f; st.h4=0.f; st.h5=0.f; }
  float pr = prod_step(st, pe);
  conv_update(st, pr);
}

__global__ void __launch_bounds__(32)
gr4j_kernel(const float2* __restrict__ pe, const float4* __restrict__ prm,
            float* __restrict__ out){
  int b = blockIdx.x * blockDim.x + threadIdx.x;
  float4 pm = prm[b];

  St st;
  st.x1 = fmaf(pm.x, 1100.f, 100.f);
  st.x2 = fmaf(pm.y,    8.f,  -5.f);
  float x3 = fmaf(pm.z, 280.f,  20.f);
  float x4 = fmaf(pm.w,  1.8f,  1.1f);
  st.inv_x1 = 1.f / st.x1;
  st.inv_x3 = 1.f / x3;
  st.s = 0.5f * st.x1;
  st.r = 0.5f * x3;

  // UH kernels (one-time, full precision)
  float ix4 = 1.f / x4;
  float sh1[4], sh2[7];
  #pragma unroll
  for (int t = 0; t < 4; t++){
    float a = fminf((float)t * ix4, 1.f);
    sh1[t] = a * a * sqrtf(a);                       // a^2.5
  }
  #pragma unroll
  for (int t = 0; t < 7; t++){
    float rr = (float)t * ix4; float v;
    if ((float)t <= x4){ v = 0.5f * rr * rr * sqrtf(rr); }
    else { float m = fmaxf(2.f - rr, 0.f); v = 1.f - 0.5f * m * m * sqrtf(m); }
    sh2[t] = v;
  }
  st.u10 = sh1[1]-sh1[0]; st.u11 = sh1[2]-sh1[1]; st.u12 = sh1[3]-sh1[2];
  st.u20 = sh2[1]-sh2[0]; st.u21 = sh2[2]-sh2[1]; st.u22 = sh2[3]-sh2[2];
  st.u23 = sh2[4]-sh2[3]; st.u24 = sh2[5]-sh2[4]; st.u25 = sh2[6]-sh2[5];
  st.h1=0.f; st.h2=0.f; st.h3=0.f; st.h4=0.f; st.h5=0.f;

  // Peel t=0: production only (its routing happens in iteration t=1).
  float2 pe0 = pe[b];
  float pr0 = prod_step(st, pe0);
  conv_update(st, pr0);

  // Blocked main loop, t = 1..4008 in 501 blocks of 8, prefetching next block.
  float2 cur[8], nxt[8];
  #pragma unroll
  for (int j = 0; j < 8; j++) cur[j] = pe[(1 + j) * NBAS + b];

  int t = 1;
  for (int blk = 0; blk < 501; blk++){
    #pragma unroll
    for (int j = 0; j < 8; j++){
      int tt = t + 8 + j;
      nxt[j] = (tt < T_TOTAL) ? pe[tt * NBAS + b] : make_float2(0.f, 0.f);
    }
    #pragma unroll
    for (int j = 0; j < 8; j++) iter(st, t + j, cur[j], out, b);
    #pragma unroll
    for (int j = 0; j < 8; j++) cur[j] = nxt[j];
    t += 8;
  }

  // Tail: t = 4009..4014 (6 steps), data already in cur[0..5].
  #pragma unroll
  for (int j = 0; j < 6; j++) iter(st, t + j, cur[j], out, b);

  // Flush routing for the final step t = 4014.
  float qlast = route_step(st);
  out[(T_TOTAL - 1 - NWARM) * NBAS + b] = qlast;
}

extern "C" void kernel_launch(void* const* d_in, const int* in_sizes, int n_in,
                              void* d_out, int out_size){
  // p_and_e is the large input (4015*2048*2), parameters the small one (2048*4).
  const void* a = d_in[0];
  const void* c = d_in[1];
  const float2* pe;
  const float4* prm;
  if (in_sizes[0] > in_sizes[1]) { pe = (const float2*)a; prm = (const float4*)c; }
  else                           { pe = (const float2*)c; prm = (const float4*)a; }
  gr4j_kernel<<<NBAS / 32, 32>>>(pe, prm, (float*)d_out);
}

// round 2
// speedup vs baseline: 1.1643x; 1.1643x over previous
#include <cuda_runtime.h>

#define T_TOTAL 4015
#define NWARM   365
#define NBAS    2048

__device__ __forceinline__ float sqrt_ap(float x){ float y; asm("sqrt.approx.f32 %0, %1;" : "=f"(y) : "f"(x)); return y; }
__device__ __forceinline__ float rsqrt_ap(float x){ float y; asm("rsqrt.approx.f32 %0, %1;" : "=f"(y) : "f"(x)); return y; }

struct St {
  float s, r;
  float x1, inv_x1;
  float c49;    // (4/9) * inv_x1
  float c35;    // x2 * ix3^3.5
  float ix3_4;  // ix3^4
  float u10,u11,u12;
  float u20,u21,u22,u23,u24,u25;
  float h1,h2,h3,h4,h5;   // pr history
  float q9p,q1p;          // pending conv outputs for the step awaiting routing
};

// Production store. tanh args <= 0.01 -> 2-term Taylor (err ~1e-11).
// Denominators are 1+d with d <= 0.01 -> 1/(1+d) ~= 1-d+d^2 (err ~1e-6).
// (1+z^4)^(-1/4) with z^4 <= 0.039 -> 4-term Taylor (err ~2e-7 abs).
// s2 clip is provably inactive (ps <= 0.02*(x1-s), es <= 0.02*s).
__device__ __forceinline__ float prod_step(St& st, float2 pe){
  float pn = fmaxf(pe.x - pe.y, 0.f);
  float en = fmaxf(pe.y - pe.x, 0.f);
  float xp = pn * st.inv_x1;
  float xe = en * st.inv_x1;
  float tp = xp * fmaf(xp*xp, -(1.f/3.f), 1.f);
  float te = xe * fmaf(xe*xe, -(1.f/3.f), 1.f);
  float u  = st.s * st.inv_x1;
  float dp = u * tp;
  float ip = fmaf(dp, dp - 1.f, 1.f);                 // ~ 1/(1+u*tp)
  float ps = st.x1 * fmaf(-u, u, 1.f) * tp * ip;
  float de = (1.f - u) * te;
  float ie = fmaf(de, de - 1.f, 1.f);                 // ~ 1/(1+(1-u)*te)
  float es = st.s * (2.f - u) * te * ie;
  float s2 = (st.s - es) + ps;
  float m  = s2 * st.c49;                             // (4/9)(s2/x1)
  float m2 = m * m;
  float y  = m2 * m2;
  float p  = fmaf(y, fmaf(y, -15.f/128.f, 5.f/32.f), -0.25f);
  float w  = fmaf(y, p, 1.f);                         // (1+y)^(-1/4)
  float snew = s2 * w;
  float pr = (s2 - snew) + (pn - ps);
  st.s = snew;
  return pr;
}

// Routing store. gex = x2*(r/x3)^3.5 = c35 * r^3 * sqrt(r).
// (1+wv^4)^(-1/4) via wv^4 = r2^4 * ix3^4 (hoisted), sqrt+rsqrt approx.
// r clip provably inactive (rnew in [0, x3]).
template<bool WANTQ>
__device__ __forceinline__ float route_step(St& st){
  float r   = st.r;
  float gex = st.c35 * (r * r * r) * sqrt_ap(r);
  float rr  = fmaxf(0.f, (r + st.q9p) + gex);
  float t2  = rr * rr;
  float a   = fmaf(t2 * t2, st.ix3_4, 1.f);
  float w   = rsqrt_ap(sqrt_ap(a));
  float rnew = rr * w;
  st.r = rnew;
  if (WANTQ) return (rr - rnew) + fmaxf(0.f, st.q1p + gex);
  return 0.f;
}

__device__ __forceinline__ void conv_update(St& st, float pr){
  st.q9p = st.u10*pr + st.u11*st.h1 + st.u12*st.h2;
  st.q1p = st.u20*pr + st.u21*st.h1 + st.u22*st.h2
         + st.u23*st.h3 + st.u24*st.h4 + st.u25*st.h5;
  st.h5 = st.h4; st.h4 = st.h3; st.h3 = st.h2; st.h2 = st.h1; st.h1 = pr;
}

template<bool STORE>
__device__ __forceinline__ void iter(St& st, float2 pe, float* op){
  float q = route_step<STORE>(st);
  if (STORE) *op = q;
  float pr = prod_step(st, pe);
  conv_update(st, pr);
}

__global__ void __launch_bounds__(32)
gr4j_kernel(const float2* __restrict__ pe, const float4* __restrict__ prm,
            float* __restrict__ out){
  int b = blockIdx.x * 32 + threadIdx.x;
  float4 pm = prm[b];

  St st;
  st.x1 = fmaf(pm.x, 1100.f, 100.f);
  float x2 = fmaf(pm.y,   8.f,  -5.f);
  float x3 = fmaf(pm.z, 280.f,  20.f);
  float x4 = fmaf(pm.w,  1.8f,  1.1f);
  st.inv_x1 = 1.f / st.x1;
  float ix3 = 1.f / x3;
  st.c49   = (4.f/9.f) * st.inv_x1;
  st.c35   = x2 * (ix3*ix3*ix3) * sqrtf(ix3);   // x2 * ix3^3.5
  float i2 = ix3 * ix3;
  st.ix3_4 = i2 * i2;
  st.s = 0.5f * st.x1;
  st.r = 0.5f * x3;

  // UH kernels (one-time, full precision)
  float ix4 = 1.f / x4;
  float sh1[4], sh2[7];
  #pragma unroll
  for (int t = 0; t < 4; t++){
    float a = fminf((float)t * ix4, 1.f);
    sh1[t] = a * a * sqrtf(a);
  }
  #pragma unroll
  for (int t = 0; t < 7; t++){
    float rr = (float)t * ix4; float v;
    if ((float)t <= x4){ v = 0.5f * rr * rr * sqrtf(rr); }
    else { float mm = fmaxf(2.f - rr, 0.f); v = 1.f - 0.5f * mm * mm * sqrtf(mm); }
    sh2[t] = v;
  }
  st.u10 = sh1[1]-sh1[0]; st.u11 = sh1[2]-sh1[1]; st.u12 = sh1[3]-sh1[2];
  st.u20 = sh2[1]-sh2[0]; st.u21 = sh2[2]-sh2[1]; st.u22 = sh2[3]-sh2[2];
  st.u23 = sh2[4]-sh2[3]; st.u24 = sh2[5]-sh2[4]; st.u25 = sh2[6]-sh2[5];
  st.h1=0.f; st.h2=0.f; st.h3=0.f; st.h4=0.f; st.h5=0.f;

  // Peel t=0: production only.
  {
    float2 pe0 = pe[b];
    float pr0 = prod_step(st, pe0);
    conv_update(st, pr0);
  }

  float2 cur[8], nxt[8];
  #pragma unroll
  for (int j = 0; j < 8; j++) cur[j] = pe[(1 + j) * NBAS + b];

  int t = 1;
  // Warmup blocks: t = 1..360 (routes 0..359, no stores).
  for (int blk = 0; blk < 45; blk++){
    #pragma unroll
    for (int j = 0; j < 8; j++) nxt[j] = pe[(t + 8 + j) * NBAS + b];
    #pragma unroll
    for (int j = 0; j < 8; j++) iter<false>(st, cur[j], nullptr);
    #pragma unroll
    for (int j = 0; j < 8; j++) cur[j] = nxt[j];
    t += 8;
  }

  // Straddling block: t = 361..368.
  #pragma unroll
  for (int j = 0; j < 8; j++) nxt[j] = pe[(t + 8 + j) * NBAS + b];
  iter<false>(st, cur[0], nullptr);   // t=361
  iter<false>(st, cur[1], nullptr);   // t=362
  iter<false>(st, cur[2], nullptr);   // t=363
  iter<false>(st, cur[3], nullptr);   // t=364
  // Boundary t=365: route(364) (discard q), reset conv history, prod(365).
  {
    route_step<false>(st);
    st.h1=0.f; st.h2=0.f; st.h3=0.f; st.h4=0.f; st.h5=0.f;
    float pr = prod_step(st, cur[4]);
    conv_update(st, pr);
  }
  float* op = out + b;
  iter<true>(st, cur[5], op); op += NBAS;   // t=366 -> stores q(365) at idx 0
  iter<true>(st, cur[6], op); op += NBAS;   // t=367
  iter<true>(st, cur[7], op); op += NBAS;   // t=368
  #pragma unroll
  for (int j = 0; j < 8; j++) cur[j] = nxt[j];
  t += 8;  // t = 369

  // Main blocks: t = 369..4008 (455 blocks of 8), unconditional stores.
  for (int blk = 0; blk < 455; blk++){
    #pragma unroll
    for (int j = 0; j < 8; j++){
      int tt = t + 8 + j;
      tt = tt < T_TOTAL ? tt : T_TOTAL - 1;   // clamp; clamped values unused
      nxt[j] = pe[tt * NBAS + b];
    }
    #pragma unroll
    for (int j = 0; j < 8; j++) iter<true>(st, cur[j], op + j * NBAS);
    op += 8 * NBAS;
    #pragma unroll
    for (int j = 0; j < 8; j++) cur[j] = nxt[j];
    t += 8;
  }

  // Tail: t = 4009..4014 (data already in cur[0..5]).
  #pragma unroll
  for (int j = 0; j < 6; j++){ iter<true>(st, cur[j], op); op += NBAS; }

  // Flush routing for the final step t = 4014 -> idx 3649.
  float qlast = route_step<true>(st);
  *op = qlast;
}

extern "C" void kernel_launch(void* const* d_in, const int* in_sizes, int n_in,
                              void* d_out, int out_size){
  const void* a = d_in[0];
  const void* c = d_in[1];
  const float2* pe;
  const float4* prm;
  if (in_sizes[0] > in_sizes[1]) { pe = (const float2*)a; prm = (const float4*)c; }
  else                           { pe = (const float2*)c; prm = (const float4*)a; }
  gr4j_kernel<<<NBAS / 32, 32>>>(pe, prm, (float*)d_out);
}

// round 3
// speedup vs baseline: 1.7741x; 1.5238x over previous
#include <cuda_runtime.h>

#define NBAS   2048
#define CHUNK  16
// 4015 = 250 full chunks + 15-step tail
#define NFULL  250

__device__ __forceinline__ float sqrt_ap(float x){ float y; asm("sqrt.approx.f32 %0, %1;" : "=f"(y) : "f"(x)); return y; }
__device__ __forceinline__ float rsqrt_ap(float x){ float y; asm("rsqrt.approx.f32 %0, %1;" : "=f"(y) : "f"(x)); return y; }

// Named-barrier producer/consumer handshake (64 threads per block, 2 warps).
// FULL(k) = 1 + (k&1), FREE(k) = 3 + (k&1).
__device__ __forceinline__ void bar_sync_id(int id){ asm volatile("bar.sync %0, 64;" :: "r"(id)); }
__device__ __forceinline__ void bar_arrive_id(int id){ asm volatile("bar.arrive %0, 64;" :: "r"(id)); }

// ---------------- production (s store) ----------------
// tanh(x) ~ x for x <= 0.01 (rel err <= 3.3e-5); 1/(1+d) ~ 1-d+d^2, d <= 0.01;
// (1+y)^(-1/4), y <= 0.039 -> 4-term Taylor. s2 clip provably inactive.
struct PSt { float s, x1, inv_x1, c49; };

__device__ __forceinline__ float prod_step(PSt& st, float2 pe){
  float diff = pe.x - pe.y;
  float pn = fmaxf(diff, 0.f);
  float en = fmaxf(-diff, 0.f);
  float xp = pn * st.inv_x1;            // ~tanh(pn/x1)
  float xe = en * st.inv_x1;            // ~tanh(en/x1)
  float u  = st.s * st.inv_x1;
  float dp = u * xp;
  float ip = fmaf(dp, dp - 1.f, 1.f);                 // ~1/(1+u*xp)
  float ps = pn * fmaf(-u, u, 1.f) * ip;              // x1*(1-u^2)*xp*ip
  float de = (1.f - u) * xe;
  float ie = fmaf(de, de - 1.f, 1.f);                 // ~1/(1+(1-u)*xe)
  float es = st.s * (2.f - u) * xe * ie;
  float s2 = (st.s - es) + ps;
  float m  = s2 * st.c49;
  float m2 = m * m;
  float y  = m2 * m2;
  float p  = fmaf(y, fmaf(y, -15.f/128.f, 5.f/32.f), -0.25f);
  float w  = fmaf(y, p, 1.f);                         // (1+y)^(-1/4)
  float snew = s2 * w;
  float pr = (s2 - snew) + (pn - ps);
  st.s = snew;
  return pr;
}

// ---------------- routing (r store) + conv ----------------
struct RSt {
  float r, c35, ix3_4, x3unused;
  float u10,u11,u12, u20,u21,u22,u23,u24,u25;
  float h1,h2,h3,h4,h5;
};

template<bool STORE>
__device__ __forceinline__ void cons_step(RSt& st, float pr, float* op){
  float q9 = st.u10*pr + st.u11*st.h1 + st.u12*st.h2;
  float q1 = st.u20*pr + st.u21*st.h1 + st.u22*st.h2
           + st.u23*st.h3 + st.u24*st.h4 + st.u25*st.h5;
  st.h5 = st.h4; st.h4 = st.h3; st.h3 = st.h2; st.h2 = st.h1; st.h1 = pr;
  float r   = st.r;
  float gex = st.c35 * (r * r * r) * sqrt_ap(r);
  float rr  = fmaxf((r + q9) + gex, 0.f);
  float t2  = rr * rr;
  float a   = fmaf(t2 * t2, st.ix3_4, 1.f);
  float w   = rsqrt_ap(sqrt_ap(a));
  float rn  = rr * w;
  st.r = rn;
  if (STORE){
    float q = (rr - rn) + fmaxf(q1 + gex, 0.f);
    *op = q;
  }
}

__shared__ float prbuf_s[2][CHUNK][32];

__global__ void __launch_bounds__(64)
gr4j_ws(const float2* __restrict__ pe, const float4* __restrict__ prm,
        float* __restrict__ out){
  int lane = threadIdx.x & 31;
  int wid  = threadIdx.x >> 5;
  int b    = blockIdx.x * 32 + lane;
  float4 pm = prm[b];
  float x1 = fmaf(pm.x, 1100.f, 100.f);
  float x2 = fmaf(pm.y,    8.f,  -5.f);
  float x3 = fmaf(pm.z,  280.f,  20.f);
  float x4 = fmaf(pm.w,   1.8f,  1.1f);

  if (wid == 0){
    // ============ PRODUCER warp ============
    PSt st;
    st.x1 = x1;
    st.inv_x1 = 1.f / x1;
    st.c49 = (4.f/9.f) * st.inv_x1;
    st.s = 0.5f * x1;

    float2 cur[CHUNK], nxt[CHUNK];
    #pragma unroll
    for (int j = 0; j < CHUNK; j++) cur[j] = pe[j * NBAS + b];

    for (int k = 0; k < NFULL; k++){
      int tb = (k + 1) * CHUNK;
      #pragma unroll
      for (int j = 0; j < CHUNK; j++){
        int tt = tb + j; tt = tt < 4015 ? tt : 4014;
        nxt[j] = pe[tt * NBAS + b];
      }
      if (k >= 2) bar_sync_id(3 + (k & 1));
      int buf = k & 1;
      #pragma unroll
      for (int j = 0; j < CHUNK; j++){
        float pr = prod_step(st, cur[j]);
        prbuf_s[buf][j][lane] = pr;
      }
      bar_arrive_id(1 + (k & 1));
      #pragma unroll
      for (int j = 0; j < CHUNK; j++) cur[j] = nxt[j];
    }
    // tail chunk k=250 (15 steps), buf 0
    bar_sync_id(3);
    #pragma unroll
    for (int j = 0; j < 15; j++){
      float pr = prod_step(st, cur[j]);
      prbuf_s[0][j][lane] = pr;
    }
    bar_arrive_id(1);
  } else {
    // ============ CONSUMER warp ============
    RSt st;
    float ix3 = 1.f / x3;
    float i2  = ix3 * ix3;
    st.c35   = x2 * (ix3 * ix3 * ix3) * sqrtf(ix3);
    st.ix3_4 = i2 * i2;
    st.r = 0.5f * x3;

    float ix4 = 1.f / x4;
    float sh1[4], sh2[7];
    #pragma unroll
    for (int t = 0; t < 4; t++){
      float a = fminf((float)t * ix4, 1.f);
      sh1[t] = a * a * sqrtf(a);
    }
    #pragma unroll
    for (int t = 0; t < 7; t++){
      float rr = (float)t * ix4; float v;
      if ((float)t <= x4){ v = 0.5f * rr * rr * sqrtf(rr); }
      else { float mm = fmaxf(2.f - rr, 0.f); v = 1.f - 0.5f * mm * mm * sqrtf(mm); }
      sh2[t] = v;
    }
    st.u10 = sh1[1]-sh1[0]; st.u11 = sh1[2]-sh1[1]; st.u12 = sh1[3]-sh1[2];
    st.u20 = sh2[1]-sh2[0]; st.u21 = sh2[2]-sh2[1]; st.u22 = sh2[3]-sh2[2];
    st.u23 = sh2[4]-sh2[3]; st.u24 = sh2[5]-sh2[4]; st.u25 = sh2[6]-sh2[5];
    st.h1=0.f; st.h2=0.f; st.h3=0.f; st.h4=0.f; st.h5=0.f;

    float prv[CHUNK];

    // chunks 0..21: t = 0..351, no stores
    for (int k = 0; k < 22; k++){
      bar_sync_id(1 + (k & 1));
      int buf = k & 1;
      #pragma unroll
      for (int j = 0; j < CHUNK; j++) prv[j] = prbuf_s[buf][j][lane];
      bar_arrive_id(3 + (k & 1));
      #pragma unroll
      for (int j = 0; j < CHUNK; j++) cons_step<false>(st, prv[j], nullptr);
    }

    // chunk 22: t = 352..367; reset history before t=365 (j=13); store from t=365
    {
      bar_sync_id(1);                 // k=22 even -> FULL id 1
      #pragma unroll
      for (int j = 0; j < CHUNK; j++) prv[j] = prbuf_s[0][j][lane];
      bar_arrive_id(3);
      #pragma unroll
      for (int j = 0; j < 13; j++) cons_step<false>(st, prv[j], nullptr);
      st.h1=0.f; st.h2=0.f; st.h3=0.f; st.h4=0.f; st.h5=0.f;
      float* op = out + b;
      cons_step<true>(st, prv[13], op);              // t=365 -> ti=0
      cons_step<true>(st, prv[14], op + NBAS);       // ti=1
      cons_step<true>(st, prv[15], op + 2*NBAS);     // ti=2
    }

    // chunks 23..249: all store
    float* op = out + 3 * NBAS + b;
    for (int k = 23; k < NFULL; k++){
      bar_sync_id(1 + (k & 1));
      int buf = k & 1;
      #pragma unroll
      for (int j = 0; j < CHUNK; j++) prv[j] = prbuf_s[buf][j][lane];
      bar_arrive_id(3 + (k & 1));
      #pragma unroll
      for (int j = 0; j < CHUNK; j++) cons_step<true>(st, prv[j], op + j * NBAS);
      op += CHUNK * NBAS;
    }

    // tail chunk k=250: 15 steps, t=4000..4014 -> ti=3635..3649
    bar_sync_id(1);
    #pragma unroll
    for (int j = 0; j < 15; j++) prv[j] = prbuf_s[0][j][lane];
    #pragma unroll
    for (int j = 0; j < 15; j++) cons_step<true>(st, prv[j], op + j * NBAS);
  }
}

extern "C" void kernel_launch(void* const* d_in, const int* in_sizes, int n_in,
                              void* d_out, int out_size){
  const void* a = d_in[0];
  const void* c = d_in[1];
  const float2* pe;
  const float4* prm;
  if (in_sizes[0] > in_sizes[1]) { pe = (const float2*)a; prm = (const float4*)c; }
  else                           { pe = (const float2*)c; prm = (const float4*)a; }
  gr4j_ws<<<NBAS / 32, 64>>>(pe, prm, (float*)d_out);
}